// round 14
// baseline (speedup 1.0000x reference)
#include <cuda_runtime.h>
#include <cstdint>
#include <cstddef>

// ---------------------------------------------------------------------------
// SNN with cochlea front-end.  B=64, T=500, IN=256, HID=512, OUT=35.
//
// R14 = R12 pipeline (best, 474us) with ONE change: snn_main's step engine
// shrunk from 512 threads/16 warps to 128 threads/4 warps (4 neurons per
// thread, float4 state).  The per-step work left after R12 (LIF x4 layers,
// 3 ballots+counts, stores) is issue- and barrier-dominated; 4 warps issue
// it in ~1/4 the slots and pay nw=4 barrier floors (~7cy) instead of 16-warp
// drains.  The 128-thread engine incl. nibble-mask corrections is the
// R9-validated code (passed, same rel_err); R9's failure was its in-kernel
// layer-1 walk, which R12 already moved to the parallel cur1_k.
// prep_quant / cochlea_rs / cur1_k are R12 verbatim (bit-exact).
// ---------------------------------------------------------------------------

namespace {
constexpr int T_STEPS = 500;
constexpr int BATCH   = 64;
constexpr int N_IN    = 256;
constexpr int N_HID   = 512;
constexpr int N_OUT   = 35;
constexpr int BT      = BATCH * T_STEPS;
constexpr int CH2     = 50;                      // t-chunk per cur1_k CTA
constexpr float SCALEF = (float)((1.0 - 0.001) / 31.0);
constexpr size_t SPK_HID = (size_t)T_STEPS * BATCH * N_HID;
constexpr size_t SPK_OUT = (size_t)T_STEPS * BATCH * N_OUT;
constexpr int WSTR = 132;                        // padded row stride (u32)
constexpr unsigned ZOFF = 256u * WSTR;           // sentinel zero-row offset
constexpr int SW_BYTES = 257 * WSTR * 4;         // 135,696 B dynamic smem
}  // namespace

// Static device scratch (no runtime allocation).
__device__ unsigned char g_w1q[N_IN * N_HID];
__device__ float g_q2T[N_HID * N_HID];
__device__ float g_q3T[N_HID * N_HID];
__device__ float g_q4T[N_HID * N_OUT];
__device__ float g_rs2[N_HID];
__device__ float g_rs3[N_HID];
__device__ float g_rs4[N_OUT];
__device__ unsigned g_chmask[BT * 8];            // cochlea spike masks
__device__ float g_cur1[(size_t)BT * N_HID];     // 65.5 MB layer-1 currents

// Exact replication of reference fake_quant (fp32, round-half-even, no FMA).
__device__ __forceinline__ float quantw(float w) {
    float wc = fminf(fmaxf(w, 0.001f), 1.0f);
    float l  = rintf((wc - 0.001f) / SCALEF);
    return __fadd_rn(__fmul_rn(l, SCALEF), 0.001f);
}

// ---------------------------------------------------------------------------
__global__ void prep_quant(const float* __restrict__ W1, const float* __restrict__ W2,
                           const float* __restrict__ W3, const float* __restrict__ W4) {
    int idx = blockIdx.x * blockDim.x + threadIdx.x;
    if (idx < N_HID * N_IN) {
        int n = idx / N_IN, k = idx % N_IN;
        float wc = fminf(fmaxf(W1[idx], 0.001f), 1.0f);
        float l  = rintf((wc - 0.001f) / SCALEF);
        g_w1q[k * N_HID + n] = (unsigned char)(int)l;
    }
    if (idx < N_HID * N_HID) {
        int n = idx / N_HID, k = idx % N_HID;
        g_q2T[k * N_HID + n] = quantw(W2[idx]);
        g_q3T[k * N_HID + n] = quantw(W3[idx]);
    }
    if (idx < N_OUT * N_HID) {
        int o = idx / N_HID, k = idx % N_HID;
        g_q4T[k * N_OUT + o] = quantw(W4[idx]);
    }
}

// Cochlea (all blocks) + rowsums (blocks 0-1).
__global__ void __launch_bounds__(256, 1) cochlea_rs(
    const float* __restrict__ x, const float* __restrict__ Wch,
    const float* __restrict__ cb)
{
    __shared__ float xs[T_STEPS];
    const int b = blockIdx.x, k = threadIdx.x;
    const int lane = k & 31, warp = k >> 5;
    for (int i = k; i < T_STEPS; i += 256) xs[i] = x[(size_t)b * T_STEPS + i];
    const float wch = Wch[k];
    const float bch = fminf(fmaxf(cb[k], 0.f), 1.f);
    float chm = 0.f;
    __syncthreads();
    for (int t = 0; t < T_STEPS; ++t) {
        float cur = __fmul_rn(xs[t], wch);
        float rst = (chm > 1.f) ? 1.f : 0.f;
        chm = __fadd_rn(__fadd_rn(__fmul_rn(bch, chm), cur), -rst);
        unsigned bal = __ballot_sync(0xffffffffu, chm > 1.f);
        if (lane == 0) g_chmask[((size_t)b * T_STEPS + t) * 8 + warp] = bal;
    }
    if (b < 2) {
        const int n = b * 256 + k;
        float s2 = 0.f, s3 = 0.f;
        for (int kk = 0; kk < N_HID; ++kk) {
            s2 = __fadd_rn(s2, g_q2T[kk * N_HID + n]);
            s3 = __fadd_rn(s3, g_q3T[kk * N_HID + n]);
        }
        g_rs2[n] = s2;
        g_rs3[n] = s3;
        if (n < N_OUT) {
            float s4 = 0.f;
            for (int kk = 0; kk < N_HID; ++kk)
                s4 = __fadd_rn(s4, g_q4T[kk * N_OUT + n]);
            g_rs4[n] = s4;
        }
    }
}

// No-op kernel: keeps snn_main at launch index 3 (mod 5) for ncu capture.
__global__ void pad_b() {}

// ---------------------------------------------------------------------------
// cur1_k: R12 verbatim (bit-exact layer-1 currents, time-parallel).
// ---------------------------------------------------------------------------
__global__ void __launch_bounds__(512, 1) cur1_k() {
    const int b    = blockIdx.x;
    const int t0   = blockIdx.y * CH2;
    const int tid  = threadIdx.x;
    const int lane = tid & 31;
    const int warp = tid >> 5;
    const unsigned ltm = (1u << lane) - 1u;

    extern __shared__ unsigned sw32[];
    __shared__ unsigned s_cm[CH2 * 8];
    __shared__ int      s_ccv[CH2];
    __shared__ __align__(16) unsigned s_list[2][264];

    for (int r = warp; r < 256; r += 16) {
        uint4 v = ((const uint4*)(g_w1q + r * N_HID))[lane];
        ((uint4*)(sw32 + r * WSTR))[lane] = v;
    }
    for (int r = tid; r < 256; r += 512) {
        unsigned* p = sw32 + r * WSTR + 128;
        p[0] = 0u; p[1] = 0u; p[2] = 0u; p[3] = 0u;
    }
    if (tid < WSTR) sw32[256 * WSTR + tid] = 0u;

    for (int i = tid; i < (CH2 * 8) / 4; i += 512)
        ((uint4*)s_cm)[i] =
            ((const uint4*)(g_chmask + ((size_t)b * T_STEPS + t0) * 8))[i];
    __syncthreads();
    if (tid < CH2) {
        uint4 a = ((const uint4*)s_cm)[2 * tid];
        uint4 c = ((const uint4*)s_cm)[2 * tid + 1];
        s_ccv[tid] = ((__popc(a.x) + __popc(a.y)) + (__popc(a.z) + __popc(a.w))) +
                     ((__popc(c.x) + __popc(c.y)) + (__popc(c.z) + __popc(c.w)));
    }
    __syncthreads();

    const int sl = lane & 3;
    const int wq = warp * 8 + (lane >> 2);
    float* outp = g_cur1 + ((size_t)b * T_STEPS + t0) * N_HID + tid;

    for (int tt = 0; tt < CH2; ++tt) {
        const int buf = tt & 1;
        const uint4 mA = ((const uint4*)s_cm)[2 * tt];
        const uint4 mB = ((const uint4*)s_cm)[2 * tt + 1];
        const int cc  = s_ccv[tt];
        const int ccq = ((cc + 31) >> 5) << 3;

        if (tid < N_IN) {
            const unsigned bal =
                (warp == 0) ? mA.x : (warp == 1) ? mA.y :
                (warp == 2) ? mA.z : (warp == 3) ? mA.w :
                (warp == 4) ? mB.x : (warp == 5) ? mB.y :
                (warp == 6) ? mB.z : mB.w;
            if ((bal >> lane) & 1u) {
                int off = __popc(bal & ltm);
                if (warp > 0) off += __popc(mA.x);
                if (warp > 1) off += __popc(mA.y);
                if (warp > 2) off += __popc(mA.z);
                if (warp > 3) off += __popc(mA.w);
                if (warp > 4) off += __popc(mB.x);
                if (warp > 5) off += __popc(mB.y);
                if (warp > 6) off += __popc(mB.z);
                s_list[buf][off] = (unsigned)tid * WSTR;
            }
        }
        if (tid < 4 * ccq - cc) s_list[buf][cc + tid] = ZOFF;
        __syncthreads();

        unsigned a02 = 0u, a13 = 0u;
        const int j0 = sl * ccq;
        #pragma unroll 1
        for (int j = j0; j < j0 + ccq; j += 8) {
            const uint4 i0 = *(const uint4*)&s_list[buf][j];
            const uint4 i1 = *(const uint4*)&s_list[buf][j + 4];
            const unsigned va = (sw32[i0.x + wq] + sw32[i0.y + wq]) +
                                (sw32[i0.z + wq] + sw32[i0.w + wq]);
            const unsigned vb = (sw32[i1.x + wq] + sw32[i1.y + wq]) +
                                (sw32[i1.z + wq] + sw32[i1.w + wq]);
            a02 += (va & 0x00FF00FFu) + (vb & 0x00FF00FFu);
            a13 += ((va >> 8) & 0x00FF00FFu) + ((vb >> 8) & 0x00FF00FFu);
        }
        a02 += __shfl_xor_sync(0xffffffffu, a02, 1);
        a13 += __shfl_xor_sync(0xffffffffu, a13, 1);
        a02 += __shfl_xor_sync(0xffffffffu, a02, 2);
        a13 += __shfl_xor_sync(0xffffffffu, a13, 2);
        const unsigned selv = (lane & 1) ? a13 : a02;
        const int lvl = (lane & 2) ? (int)(selv >> 16) : (int)(selv & 0xFFFFu);
        outp[(size_t)tt * N_HID] =
            __fadd_rn(__fmul_rn(0.001f, (float)cc), __fmul_rn(SCALEF, (float)lvl));
    }
}

// ---------------------------------------------------------------------------
// Rare-path corrections (R9-validated).  Nibble word w holds spike bits of
// neurons 16w..16w+15 at bit p (p%8 < 4): k = 16w + 4*(p>>3) + (p&7).
// Ascending p => ascending k (exact reference order).
__device__ __forceinline__ float4 correct4(const unsigned* nibw, float4 rs,
                                           const float* __restrict__ qT, int col) {
    float4 a = rs;
    int tot = 0;
    #pragma unroll 1
    for (int w = 0; w < 32; ++w) {
        unsigned m = (~nibw[w]) & 0x0F0F0F0Fu;   // zero-spike bits
        tot += __popc(m);
        while (m) {
            int p = __ffs(m) - 1; m &= m - 1;
            int k = (w << 4) + ((p >> 3) << 2) + (p & 7);
            const float4 q = *(const float4*)(qT + (size_t)k * N_HID + col);
            a.x = __fadd_rn(a.x, -q.x);
            a.y = __fadd_rn(a.y, -q.y);
            a.z = __fadd_rn(a.z, -q.z);
            a.w = __fadd_rn(a.w, -q.w);
        }
    }
    if (tot == N_HID) return make_float4(0.f, 0.f, 0.f, 0.f);
    return a;
}

__device__ __forceinline__ float correct1(const unsigned* nibw, float rs,
                                          const float* __restrict__ qT, int col) {
    float a = rs;
    int tot = 0;
    #pragma unroll 1
    for (int w = 0; w < 32; ++w) {
        unsigned m = (~nibw[w]) & 0x0F0F0F0Fu;
        tot += __popc(m);
        while (m) {
            int p = __ffs(m) - 1; m &= m - 1;
            int k = (w << 4) + ((p >> 3) << 2) + (p & 7);
            a = __fadd_rn(a, -__ldg(qT + (size_t)k * N_OUT + col));
        }
    }
    if (tot == N_HID) return 0.f;
    return a;
}

// ---------------------------------------------------------------------------
// Main recurrence: one CTA per batch element, 128 threads (4 warps).
// Thread tid owns neurons 4*tid..4*tid+3; cur1 arrives prefetched from
// g_cur1 (4-deep float4 pipeline).
// ---------------------------------------------------------------------------
__global__ void __launch_bounds__(128, 1) snn_main(
    const float* __restrict__ pb1, const float* __restrict__ pb2,
    const float* __restrict__ pb3, const float* __restrict__ pb4,
    float* __restrict__ out)
{
    const int b   = blockIdx.x;
    const int tid = threadIdx.x;

    __shared__ unsigned s_nib[3][32];            // spike nibbles per layer

    const float beta1 = fminf(fmaxf(pb1[0], 0.f), 1.f);
    const float beta2 = fminf(fmaxf(pb2[0], 0.f), 1.f);
    const float beta3 = fminf(fmaxf(pb3[0], 0.f), 1.f);
    const float beta4 = fminf(fmaxf(pb4[0], 0.f), 1.f);

    const float4 rs2v = *(const float4*)(g_rs2 + 4 * tid);
    const float4 rs3v = *(const float4*)(g_rs3 + 4 * tid);
    const float  rs4v = (tid < N_OUT) ? g_rs4[tid] : 0.f;

    float4 m1 = make_float4(0.f, 0.f, 0.f, 0.f);
    float4 m2 = m1, m3 = m1;
    float  m4 = 0.f;

    const float* curb = g_cur1 + (size_t)b * T_STEPS * N_HID;
    float4 pf[4];
    #pragma unroll
    for (int i = 0; i < 4; ++i)
        pf[i] = __ldg((const float4*)(curb + (size_t)i * N_HID) + tid);

    float* o1 = out + (size_t)b * N_HID + 4 * tid;
    float* o2 = o1 + SPK_HID;
    float* o3 = o2 + SPK_HID;
    float* o4 = out + 3 * SPK_HID + (size_t)b * N_OUT + tid;
    float* om = o4 + SPK_OUT;

    for (int t = 0; t < T_STEPS; ++t) {
        const float4 c1 = pf[t & 3];
        if (t + 4 < T_STEPS)
            pf[t & 3] = __ldg((const float4*)(curb + (size_t)(t + 4) * N_HID) + tid);

        // ---------------- layer 1 ------------------------------------------
        float r;
        r = (m1.x > 1.f) ? 1.f : 0.f; m1.x = __fadd_rn(__fadd_rn(__fmul_rn(beta1, m1.x), c1.x), -r);
        r = (m1.y > 1.f) ? 1.f : 0.f; m1.y = __fadd_rn(__fadd_rn(__fmul_rn(beta1, m1.y), c1.y), -r);
        r = (m1.z > 1.f) ? 1.f : 0.f; m1.z = __fadd_rn(__fadd_rn(__fmul_rn(beta1, m1.z), c1.z), -r);
        r = (m1.w > 1.f) ? 1.f : 0.f; m1.w = __fadd_rn(__fadd_rn(__fmul_rn(beta1, m1.w), c1.w), -r);
        bool sx = m1.x > 1.f, sy = m1.y > 1.f, sz = m1.z > 1.f, sw = m1.w > 1.f;
        const size_t tstr = (size_t)t * (BATCH * N_HID);
        *(float4*)(o1 + tstr) = make_float4(sx ? 1.f : 0.f, sy ? 1.f : 0.f,
                                            sz ? 1.f : 0.f, sw ? 1.f : 0.f);
        int nib = (int)sx | ((int)sy << 1) | ((int)sz << 2) | ((int)sw << 3);
        ((unsigned char*)s_nib[0])[tid] = (unsigned char)nib;
        int zc = __syncthreads_count(nib != 15);   // barrier #1

        // ---------------- layer 2 ------------------------------------------
        float4 c2 = (zc == 0) ? rs2v : correct4(s_nib[0], rs2v, g_q2T, 4 * tid);
        r = (m2.x > 1.f) ? 1.f : 0.f; m2.x = __fadd_rn(__fadd_rn(__fmul_rn(beta2, m2.x), c2.x), -r);
        r = (m2.y > 1.f) ? 1.f : 0.f; m2.y = __fadd_rn(__fadd_rn(__fmul_rn(beta2, m2.y), c2.y), -r);
        r = (m2.z > 1.f) ? 1.f : 0.f; m2.z = __fadd_rn(__fadd_rn(__fmul_rn(beta2, m2.z), c2.z), -r);
        r = (m2.w > 1.f) ? 1.f : 0.f; m2.w = __fadd_rn(__fadd_rn(__fmul_rn(beta2, m2.w), c2.w), -r);
        sx = m2.x > 1.f; sy = m2.y > 1.f; sz = m2.z > 1.f; sw = m2.w > 1.f;
        *(float4*)(o2 + tstr) = make_float4(sx ? 1.f : 0.f, sy ? 1.f : 0.f,
                                            sz ? 1.f : 0.f, sw ? 1.f : 0.f);
        nib = (int)sx | ((int)sy << 1) | ((int)sz << 2) | ((int)sw << 3);
        ((unsigned char*)s_nib[1])[tid] = (unsigned char)nib;
        zc = __syncthreads_count(nib != 15);       // barrier #2

        // ---------------- layer 3 ------------------------------------------
        float4 c3 = (zc == 0) ? rs3v : correct4(s_nib[1], rs3v, g_q3T, 4 * tid);
        r = (m3.x > 1.f) ? 1.f : 0.f; m3.x = __fadd_rn(__fadd_rn(__fmul_rn(beta3, m3.x), c3.x), -r);
        r = (m3.y > 1.f) ? 1.f : 0.f; m3.y = __fadd_rn(__fadd_rn(__fmul_rn(beta3, m3.y), c3.y), -r);
        r = (m3.z > 1.f) ? 1.f : 0.f; m3.z = __fadd_rn(__fadd_rn(__fmul_rn(beta3, m3.z), c3.z), -r);
        r = (m3.w > 1.f) ? 1.f : 0.f; m3.w = __fadd_rn(__fadd_rn(__fmul_rn(beta3, m3.w), c3.w), -r);
        sx = m3.x > 1.f; sy = m3.y > 1.f; sz = m3.z > 1.f; sw = m3.w > 1.f;
        *(float4*)(o3 + tstr) = make_float4(sx ? 1.f : 0.f, sy ? 1.f : 0.f,
                                            sz ? 1.f : 0.f, sw ? 1.f : 0.f);
        nib = (int)sx | ((int)sy << 1) | ((int)sz << 2) | ((int)sw << 3);
        ((unsigned char*)s_nib[2])[tid] = (unsigned char)nib;
        zc = __syncthreads_count(nib != 15);       // barrier #3

        // ---------------- layer 4 (threads 0..34) --------------------------
        if (tid < N_OUT) {
            float c4 = (zc == 0) ? rs4v : correct1(s_nib[2], rs4v, g_q4T, tid);
            r = (m4 > 1.f) ? 1.f : 0.f;
            m4 = __fadd_rn(__fadd_rn(__fmul_rn(beta4, m4), c4), -r);
            o4[(size_t)t * (BATCH * N_OUT)] = (m4 > 1.f) ? 1.f : 0.f;
            om[(size_t)t * (BATCH * N_OUT)] = m4;
        }
        // next step's barrier #1 orders nib reads vs. future writes
    }
}

// ---------------------------------------------------------------------------
// Launcher.  Inputs: x, Wch, W1, W2, W3, W4, cochlea_betas, beta1..beta4.
// Output: concat(spk1, spk2, spk3, spk4, mem4), each [T, B, F], float32.
// 5 launches per replay, snn_main at index 3 => ncu capture hits it.
// ---------------------------------------------------------------------------
extern "C" void kernel_launch(void* const* d_in, const int* in_sizes, int n_in,
                              void* d_out, int out_size) {
    const float* x   = (const float*)d_in[0];
    const float* Wch = (const float*)d_in[1];
    const float* W1  = (const float*)d_in[2];
    const float* W2  = (const float*)d_in[3];
    const float* W3  = (const float*)d_in[4];
    const float* W4  = (const float*)d_in[5];
    const float* cb  = (const float*)d_in[6];
    const float* b1  = (const float*)d_in[7];
    const float* b2  = (const float*)d_in[8];
    const float* b3  = (const float*)d_in[9];
    const float* b4  = (const float*)d_in[10];
    float* out = (float*)d_out;

    cudaFuncSetAttribute(cur1_k, cudaFuncAttributeMaxDynamicSharedMemorySize,
                         SW_BYTES);

    prep_quant<<<1024, 256>>>(W1, W2, W3, W4);            // launch 0
    cochlea_rs<<<BATCH, 256>>>(x, Wch, cb);               // launch 1
    cur1_k<<<dim3(BATCH, T_STEPS / CH2), 512, SW_BYTES>>>();  // launch 2
    snn_main<<<BATCH, 128>>>(b1, b2, b3, b4, out);        // launch 3
    pad_b<<<1, 32>>>();                                   // launch 4
}